// round 10
// baseline (speedup 1.0000x reference)
#include <cuda_runtime.h>
#include <math.h>
#include <cstdint>

#define Dm 1024
#define Ne 12
#define Nt 2048
#define HSdim 2048
#define HRdim 3072
#define TAUf 1.5f

// ---------------- scratch (static device arrays; no allocation) ----------------
__device__ float g_Aact[(long)Nt * HSdim];         // 2048 x 2048 (fused geglu out)
__device__ float g_ys[(long)Nt * Dm];              // 2048 x 1024
__device__ float g_Ar[(long)2 * Nt * HRdim];       // 4096 x 3072 (fused geglu out)
__device__ float g_yE[(long)2 * Nt * Dm];          // 4096 x 1024
__device__ int   g_top[Nt * 2];
__device__ float g_w[Nt * 2];
__device__ int   g_cnt[Ne];
__device__ int   g_offs[Ne + 1];
__device__ int   g_tokrow[2 * Nt];
__device__ int   g_slot[Nt * 2];

// ---------------- helpers ----------------
__device__ __forceinline__ uint32_t f2tf32(float x) {
    uint32_t r;
    asm("cvt.rna.tf32.f32 %0, %1;" : "=r"(r) : "f"(x));
    return r;
}
__device__ __forceinline__ void mma_tf32(float* d, const uint32_t* a, const uint32_t* b) {
    asm volatile(
        "mma.sync.aligned.m16n8k8.row.col.f32.tf32.tf32.f32 "
        "{%0,%1,%2,%3}, {%4,%5,%6,%7}, {%8,%9}, {%0,%1,%2,%3};"
        : "+f"(d[0]), "+f"(d[1]), "+f"(d[2]), "+f"(d[3])
        : "r"(a[0]), "r"(a[1]), "r"(a[2]), "r"(a[3]), "r"(b[0]), "r"(b[1]));
}
__device__ __forceinline__ float gelu_exact(float g) {
    return 0.5f * g * (1.0f + erff(g * 0.70710678118654752f));
}

// ---------------- routing ----------------
__global__ void router_kernel(const float* __restrict__ x,
                              const float* __restrict__ Wr,
                              const float* __restrict__ br) {
    int n = blockIdx.x;
    __shared__ float sx[Dm];
    __shared__ float slog[Ne];
    for (int k = threadIdx.x; k < Dm; k += blockDim.x) sx[k] = x[(long)n * Dm + k];
    __syncthreads();
    int e = threadIdx.x;
    if (e < Ne) {
        float s = 0.f;
        #pragma unroll 8
        for (int k = 0; k < Dm; k++) s += sx[k] * Wr[k * Ne + e];
        slog[e] = (s + br[e]) / TAUf;
    }
    __syncthreads();
    if (threadIdx.x == 0) {
        int i0 = 0; float v0 = slog[0];
        for (int j = 1; j < Ne; j++) if (slog[j] > v0) { v0 = slog[j]; i0 = j; }
        int i1 = -1; float v1 = -1e30f;
        for (int j = 0; j < Ne; j++) if (j != i0 && slog[j] > v1) { v1 = slog[j]; i1 = j; }
        float e1 = expf(v1 - v0);
        float z = 1.0f + e1;
        g_top[n * 2 + 0] = i0; g_top[n * 2 + 1] = i1;
        g_w[n * 2 + 0] = 1.0f / z; g_w[n * 2 + 1] = e1 / z;
    }
}

// single block: count + prefix + fill
__global__ void __launch_bounds__(1024) dispatch_kernel() {
    __shared__ int scnt[Ne], soffs[Ne];
    int tid = threadIdx.x;
    if (tid < Ne) scnt[tid] = 0;
    __syncthreads();
    int rnk[4], eid[4];
    #pragma unroll
    for (int it = 0; it < 4; it++) {
        int i = tid + it * 1024;
        eid[it] = g_top[i];
        rnk[it] = atomicAdd(&scnt[eid[it]], 1);
    }
    __syncthreads();
    if (tid == 0) {
        int o = 0;
        for (int e2 = 0; e2 < Ne; e2++) { soffs[e2] = o; o += scnt[e2]; }
    }
    __syncthreads();
    #pragma unroll
    for (int it = 0; it < 4; it++) {
        int i = tid + it * 1024;
        int r = soffs[eid[it]] + rnk[it];
        g_tokrow[r] = i >> 1;
        g_slot[i] = r;
    }
    if (tid < Ne) { g_cnt[tid] = scnt[tid]; g_offs[tid] = soffs[tid]; }
    if (tid == 0) g_offs[Ne] = 2 * Nt;
}

// ---------------- TF32 mma.sync GEMM, double-buffered smem pipeline ----------------
// FUSED=false: C[(rowbase+r)][n] = sum_k A[row(r)][k]*B[k][n] + bias[n],  C stride W==N
// FUSED=true : B has width N=2W; tile cols interleave 8-col act/gate groups;
//              epilogue writes C[r][j] = (act+ba)*gelu(gate+bg), C stride W.
#define BM 128
#define BN 128
#define BK 32
#define SSTR 136
#define HALF (2 * BK * SSTR)                 // words per buffer (A+B)
#define GEMM_SMEM_BYTES (2 * HALF * 4)       // 69632 B

template <bool FUSED>
__global__ void __launch_bounds__(256, 1)
tf32gemm(const float* __restrict__ A,
         const float* __restrict__ Bb,
         const float* __restrict__ biasb,
         float* __restrict__ C,
         int Mfixed, int N, int W, int K,
         const int* __restrict__ cnt,
         const int* __restrict__ offs,
         const int* __restrict__ rowidx,
         long strideB, int strideBias) {
    extern __shared__ float sm[];

    int tid = threadIdx.x;
    int w = tid >> 5, l = tid & 31;
    int g = l >> 2, c = l & 3;
    int wm = w >> 2, wn = w & 3;             // warp grid 2 x 4

    int e = blockIdx.z;
    int M, rowbase;
    if (cnt) { M = cnt[e]; rowbase = offs[e]; }
    else     { M = Mfixed; rowbase = 0; }
    const float* B = Bb + (long)e * strideB;
    const float* bias = biasb + (long)e * strideBias;
    int bn = blockIdx.x * (FUSED ? 64 : BN);

    // A loader: row am, k offset akoff (+0/+16)
    int am = tid & 127;
    int akoff = (tid >> 7) * 16;
    // B loader: fixed tile col n4, rows bkk + i*8
    int n4 = l << 2;
    int bkk = tid >> 5;
    int gcolB;
    if (FUSED) {
        int grp = n4 >> 4, sub = n4 & 15;
        gcolB = bn + grp * 8 + sub + (sub >= 8 ? (W - 8) : 0);
    } else {
        gcolB = bn + n4;
    }

    for (int bm = blockIdx.y * BM; bm < M; bm += gridDim.y * BM) {
        int r = bm + am;
        if (r >= M) r = bm;
        long ga = rowidx ? (long)rowidx[rowbase + r] : (long)(rowbase + r);
        const float* Arow = A + ga * (long)K;

        float acc[4][4][4];
        #pragma unroll
        for (int mt = 0; mt < 4; mt++)
            #pragma unroll
            for (int nt = 0; nt < 4; nt++)
                #pragma unroll
                for (int i = 0; i < 4; i++) acc[mt][nt][i] = 0.f;

        float4 pa[4], pb[4];
        // prologue: fetch k0=0 tile
        #pragma unroll
        for (int i = 0; i < 4; i++)
            pa[i] = *(const float4*)(Arow + akoff + i * 4);
        #pragma unroll
        for (int i = 0; i < 4; i++)
            pb[i] = *(const float4*)(B + (long)(bkk + i * 8) * N + gcolB);
        {
            float* As = sm;
            float* Bs = sm + BK * SSTR;
            #pragma unroll
            for (int i = 0; i < 4; i++) {
                int kk = akoff + i * 4;
                As[(kk + 0) * SSTR + am] = __uint_as_float(f2tf32(pa[i].x));
                As[(kk + 1) * SSTR + am] = __uint_as_float(f2tf32(pa[i].y));
                As[(kk + 2) * SSTR + am] = __uint_as_float(f2tf32(pa[i].z));
                As[(kk + 3) * SSTR + am] = __uint_as_float(f2tf32(pa[i].w));
            }
            #pragma unroll
            for (int i = 0; i < 4; i++) {
                float4 o;
                o.x = __uint_as_float(f2tf32(pb[i].x));
                o.y = __uint_as_float(f2tf32(pb[i].y));
                o.z = __uint_as_float(f2tf32(pb[i].z));
                o.w = __uint_as_float(f2tf32(pb[i].w));
                *(float4*)&Bs[(bkk + i * 8) * SSTR + n4] = o;
            }
        }

        int buf = 0;
        for (int k0 = 0; k0 < K; k0 += BK) {
            __syncthreads();
            bool more = (k0 + BK) < K;
            if (more) {
                int kn = k0 + BK;
                #pragma unroll
                for (int i = 0; i < 4; i++)
                    pa[i] = *(const float4*)(Arow + kn + akoff + i * 4);
                #pragma unroll
                for (int i = 0; i < 4; i++)
                    pb[i] = *(const float4*)(B + (long)(kn + bkk + i * 8) * N + gcolB);
            }
            // MMA on current buffer
            {
                const float* As = sm + buf * HALF;
                const float* Bs = As + BK * SSTR;
                #pragma unroll
                for (int ks = 0; ks < 4; ks++) {
                    int kk = ks * 8;
                    uint32_t af[4][4], bf[4][2];
                    #pragma unroll
                    for (int mt = 0; mt < 4; mt++) {
                        int rm = wm * 64 + mt * 16;
                        af[mt][0] = __float_as_uint(As[(kk + c) * SSTR + rm + g]);
                        af[mt][1] = __float_as_uint(As[(kk + c) * SSTR + rm + g + 8]);
                        af[mt][2] = __float_as_uint(As[(kk + c + 4) * SSTR + rm + g]);
                        af[mt][3] = __float_as_uint(As[(kk + c + 4) * SSTR + rm + g + 8]);
                    }
                    #pragma unroll
                    for (int nt = 0; nt < 4; nt++) {
                        int cn = wn * 32 + nt * 8;
                        bf[nt][0] = __float_as_uint(Bs[(kk + c) * SSTR + cn + g]);
                        bf[nt][1] = __float_as_uint(Bs[(kk + c + 4) * SSTR + cn + g]);
                    }
                    #pragma unroll
                    for (int mt = 0; mt < 4; mt++)
                        #pragma unroll
                        for (int nt = 0; nt < 4; nt++)
                            mma_tf32(acc[mt][nt], af[mt], bf[nt]);
                }
            }
            // store next tile into the other buffer
            if (more) {
                float* As = sm + (buf ^ 1) * HALF;
                float* Bs = As + BK * SSTR;
                #pragma unroll
                for (int i = 0; i < 4; i++) {
                    int kk = akoff + i * 4;
                    As[(kk + 0) * SSTR + am] = __uint_as_float(f2tf32(pa[i].x));
                    As[(kk + 1) * SSTR + am] = __uint_as_float(f2tf32(pa[i].y));
                    As[(kk + 2) * SSTR + am] = __uint_as_float(f2tf32(pa[i].z));
                    As[(kk + 3) * SSTR + am] = __uint_as_float(f2tf32(pa[i].w));
                }
                #pragma unroll
                for (int i = 0; i < 4; i++) {
                    float4 o;
                    o.x = __uint_as_float(f2tf32(pb[i].x));
                    o.y = __uint_as_float(f2tf32(pb[i].y));
                    o.z = __uint_as_float(f2tf32(pb[i].z));
                    o.w = __uint_as_float(f2tf32(pb[i].w));
                    *(float4*)&Bs[(bkk + i * 8) * SSTR + n4] = o;
                }
            }
            buf ^= 1;
        }

        // ---- epilogue ----
        if (FUSED) {
            #pragma unroll
            for (int mt = 0; mt < 4; mt++) {
                int rm0 = bm + wm * 64 + mt * 16 + g;
                #pragma unroll
                for (int np = 0; np < 2; np++) {
                    int j0 = bn + (2 * wn + np) * 8 + 2 * c;
                    float2 ba = *(const float2*)(bias + j0);
                    float2 bg = *(const float2*)(bias + W + j0);
                    float* a = acc[mt][2 * np];
                    float* gt = acc[mt][2 * np + 1];
                    if (rm0 < M) {
                        float2 o;
                        o.x = (a[0] + ba.x) * gelu_exact(gt[0] + bg.x);
                        o.y = (a[1] + ba.y) * gelu_exact(gt[1] + bg.y);
                        *(float2*)(C + (long)(rowbase + rm0) * W + j0) = o;
                    }
                    if (rm0 + 8 < M) {
                        float2 o;
                        o.x = (a[2] + ba.x) * gelu_exact(gt[2] + bg.x);
                        o.y = (a[3] + ba.y) * gelu_exact(gt[3] + bg.y);
                        *(float2*)(C + (long)(rowbase + rm0 + 8) * W + j0) = o;
                    }
                }
            }
        } else {
            #pragma unroll
            for (int mt = 0; mt < 4; mt++) {
                int rm0 = bm + wm * 64 + mt * 16 + g;
                #pragma unroll
                for (int nt = 0; nt < 4; nt++) {
                    int col = bn + wn * 32 + nt * 8 + 2 * c;
                    float2 bv = *(const float2*)(bias + col);
                    if (rm0 < M) {
                        float2 o;
                        o.x = acc[mt][nt][0] + bv.x;
                        o.y = acc[mt][nt][1] + bv.y;
                        *(float2*)(C + (long)(rowbase + rm0) * W + col) = o;
                    }
                    if (rm0 + 8 < M) {
                        float2 o;
                        o.x = acc[mt][nt][2] + bv.x;
                        o.y = acc[mt][nt][3] + bv.y;
                        *(float2*)(C + (long)(rowbase + rm0 + 8) * W + col) = o;
                    }
                }
            }
        }
        __syncthreads();   // protect smem before next bm-tile prologue
    }
}

// ---------------- combine: out = ys + w0*yE[slot0] + w1*yE[slot1] ----------------
__global__ void combine_kernel(const float* __restrict__ ys,
                               const float* __restrict__ yE,
                               float* __restrict__ out) {
    int idx = blockIdx.x * blockDim.x + threadIdx.x;  // over Nt*Dm/4
    int n = idx >> 8;
    int d4 = (idx & 255) << 2;
    int s0 = g_slot[n * 2 + 0], s1 = g_slot[n * 2 + 1];
    float w0 = g_w[n * 2 + 0], w1 = g_w[n * 2 + 1];
    float4 a = *(const float4*)(ys + (long)n * Dm + d4);
    float4 b = *(const float4*)(yE + (long)s0 * Dm + d4);
    float4 cc = *(const float4*)(yE + (long)s1 * Dm + d4);
    float4 o;
    o.x = a.x + w0 * b.x + w1 * cc.x;
    o.y = a.y + w0 * b.y + w1 * cc.y;
    o.z = a.z + w0 * b.z + w1 * cc.z;
    o.w = a.w + w0 * b.w + w1 * cc.w;
    *(float4*)(out + (long)n * Dm + d4) = o;
}

// ---------------- launch ----------------
extern "C" void kernel_launch(void* const* d_in, const int* in_sizes, int n_in,
                              void* d_out, int out_size) {
    const float* x   = (const float*)d_in[0];
    const float* Ws1 = (const float*)d_in[1];
    const float* bs1 = (const float*)d_in[2];
    const float* Ws2 = (const float*)d_in[3];
    const float* bs2 = (const float*)d_in[4];
    const float* We1 = (const float*)d_in[5];
    const float* be1 = (const float*)d_in[6];
    const float* We2 = (const float*)d_in[7];
    const float* be2 = (const float*)d_in[8];
    const float* Wr  = (const float*)d_in[9];
    const float* br  = (const float*)d_in[10];
    float* out = (float*)d_out;

    float *pAact, *pys, *pAr, *pyE;
    int *pcnt, *poffs, *ptok;
    cudaGetSymbolAddress((void**)&pAact, g_Aact);
    cudaGetSymbolAddress((void**)&pys,   g_ys);
    cudaGetSymbolAddress((void**)&pAr,   g_Ar);
    cudaGetSymbolAddress((void**)&pyE,   g_yE);
    cudaGetSymbolAddress((void**)&pcnt,  g_cnt);
    cudaGetSymbolAddress((void**)&poffs, g_offs);
    cudaGetSymbolAddress((void**)&ptok,  g_tokrow);

    cudaFuncSetAttribute(tf32gemm<true>,  cudaFuncAttributeMaxDynamicSharedMemorySize, GEMM_SMEM_BYTES);
    cudaFuncSetAttribute(tf32gemm<false>, cudaFuncAttributeMaxDynamicSharedMemorySize, GEMM_SMEM_BYTES);

    // 1) routing
    router_kernel<<<Nt, 128>>>(x, Wr, br);
    dispatch_kernel<<<1, 1024>>>();

    // 2) GEMM1 (fused GEGLU): shared then routed
    tf32gemm<true><<<dim3(HSdim / 64, Nt / BM, 1), 256, GEMM_SMEM_BYTES>>>(
        x, Ws1, bs1, pAact, Nt, 2 * HSdim, HSdim, Dm,
        nullptr, nullptr, nullptr, 0, 0);
    tf32gemm<true><<<dim3(HRdim / 64, 3, Ne), 256, GEMM_SMEM_BYTES>>>(
        x, We1, be1, pAr, 0, 2 * HRdim, HRdim, Dm,
        pcnt, poffs, ptok, (long)Dm * 2 * HRdim, 2 * HRdim);

    // 3) GEMM2: shared then routed
    tf32gemm<false><<<dim3(Dm / BN, Nt / BM, 1), 256, GEMM_SMEM_BYTES>>>(
        pAact, Ws2, bs2, pys, Nt, Dm, Dm, HSdim,
        nullptr, nullptr, nullptr, 0, 0);
    tf32gemm<false><<<dim3(Dm / BN, 4, Ne), 256, GEMM_SMEM_BYTES>>>(
        pAr, We2, be2, pyE, 0, Dm, Dm, HRdim,
        pcnt, poffs, nullptr, (long)HRdim * Dm, Dm);

    // 4) combine
    combine_kernel<<<(Nt * Dm / 4) / 256, 256>>>(pys, pyE, out);
}

// round 11
// speedup vs baseline: 1.0648x; 1.0648x over previous
#include <cuda_runtime.h>
#include <math.h>
#include <cstdint>

#define Dm 1024
#define Ne 12
#define Nt 2048
#define HSdim 2048
#define HRdim 3072
#define TAUf 1.5f

// ---------------- scratch ----------------
__device__ float g_Aact[(long)Nt * HSdim];
__device__ float g_ys[(long)Nt * Dm];
__device__ float g_Ar[(long)2 * Nt * HRdim];
__device__ float g_yE[(long)2 * Nt * Dm];
__device__ int   g_top[Nt * 2];
__device__ float g_w[Nt * 2];
__device__ int   g_cnt[Ne];
__device__ int   g_offs[Ne + 1];
__device__ int   g_tokrow[2 * Nt];
__device__ int   g_slot[Nt * 2];

// ---------------- helpers ----------------
__device__ __forceinline__ uint32_t smem_u32(const void* p) {
    uint32_t a;
    asm("{ .reg .u64 t; cvta.to.shared.u64 t, %1; cvt.u32.u64 %0, t; }" : "=r"(a) : "l"(p));
    return a;
}
__device__ __forceinline__ uint32_t f2tf32(float x) {
    uint32_t r;
    asm("cvt.rna.tf32.f32 %0, %1;" : "=r"(r) : "f"(x));
    return r;
}
__device__ __forceinline__ void mma_tf32(float* d, const uint32_t* a, const uint32_t* b) {
    asm volatile(
        "mma.sync.aligned.m16n8k8.row.col.f32.tf32.tf32.f32 "
        "{%0,%1,%2,%3}, {%4,%5,%6,%7}, {%8,%9}, {%0,%1,%2,%3};"
        : "+f"(d[0]), "+f"(d[1]), "+f"(d[2]), "+f"(d[3])
        : "r"(a[0]), "r"(a[1]), "r"(a[2]), "r"(a[3]), "r"(b[0]), "r"(b[1]));
}
__device__ __forceinline__ void cpa16(uint32_t dst, const void* src) {
    asm volatile("cp.async.cg.shared.global [%0], [%1], 16;" :: "r"(dst), "l"(src));
}
#define CPA_COMMIT() asm volatile("cp.async.commit_group;" ::: "memory")
#define CPA_WAIT0()  asm volatile("cp.async.wait_group 0;" ::: "memory")
__device__ __forceinline__ float gelu_exact(float g) {
    return 0.5f * g * (1.0f + erff(g * 0.70710678118654752f));
}
// swizzled smem word indices (conflict-free, 16B-contiguity preserving)
__device__ __forceinline__ int swzA(int m, int k) { return m * 32 + (k ^ ((m & 7) << 2)); }
__device__ __forceinline__ int swzB(int k, int n) { return k * 128 + (n ^ ((k & 3) << 3)); }

// ---------------- routing ----------------
__global__ void router_kernel(const float* __restrict__ x,
                              const float* __restrict__ Wr,
                              const float* __restrict__ br) {
    int n = blockIdx.x;
    __shared__ float sx[Dm];
    __shared__ float slog[Ne];
    for (int k = threadIdx.x; k < Dm; k += blockDim.x) sx[k] = x[(long)n * Dm + k];
    __syncthreads();
    int e = threadIdx.x;
    if (e < Ne) {
        float s = 0.f;
        #pragma unroll 8
        for (int k = 0; k < Dm; k++) s += sx[k] * Wr[k * Ne + e];
        slog[e] = (s + br[e]) / TAUf;
    }
    __syncthreads();
    if (threadIdx.x == 0) {
        int i0 = 0; float v0 = slog[0];
        for (int j = 1; j < Ne; j++) if (slog[j] > v0) { v0 = slog[j]; i0 = j; }
        int i1 = -1; float v1 = -1e30f;
        for (int j = 0; j < Ne; j++) if (j != i0 && slog[j] > v1) { v1 = slog[j]; i1 = j; }
        float e1 = expf(v1 - v0);
        float z = 1.0f + e1;
        g_top[n * 2 + 0] = i0; g_top[n * 2 + 1] = i1;
        g_w[n * 2 + 0] = 1.0f / z; g_w[n * 2 + 1] = e1 / z;
    }
}

__global__ void __launch_bounds__(1024) dispatch_kernel() {
    __shared__ int scnt[Ne], soffs[Ne];
    int tid = threadIdx.x;
    if (tid < Ne) scnt[tid] = 0;
    __syncthreads();
    int rnk[4], eid[4];
    #pragma unroll
    for (int it = 0; it < 4; it++) {
        int i = tid + it * 1024;
        eid[it] = g_top[i];
        rnk[it] = atomicAdd(&scnt[eid[it]], 1);
    }
    __syncthreads();
    if (tid == 0) {
        int o = 0;
        for (int e2 = 0; e2 < Ne; e2++) { soffs[e2] = o; o += scnt[e2]; }
    }
    __syncthreads();
    #pragma unroll
    for (int it = 0; it < 4; it++) {
        int i = tid + it * 1024;
        int r = soffs[eid[it]] + rnk[it];
        g_tokrow[r] = i >> 1;
        g_slot[i] = r;
    }
    if (tid < Ne) { g_cnt[tid] = scnt[tid]; g_offs[tid] = soffs[tid]; }
    if (tid == 0) g_offs[Ne] = 2 * Nt;
}

// ---------------- TF32 mma.sync GEMM, cp.async 2-stage, 64x64 warp tiles ----------------
// CTA tile 128x128x32. 128 threads = 4 warps (2x2). Stage = A(4096w) + B(4096w).
#define BM 128
#define BK 32
#define STAGE_W 8192
#define GEMM_SMEM_BYTES (2 * STAGE_W * 4)   // 65536

template <bool FUSED>
__global__ void __launch_bounds__(128, 2)
tf32gemm(const float* __restrict__ A,
         const float* __restrict__ Bb,
         const float* __restrict__ biasb,
         float* __restrict__ C,
         int Mfixed, int N, int W, int K,
         const int* __restrict__ cnt,
         const int* __restrict__ offs,
         const int* __restrict__ rowidx,
         long strideB, int strideBias) {
    extern __shared__ float sm[];
    uint32_t sb = smem_u32(sm);

    int tid = threadIdx.x;
    int w = tid >> 5, l = tid & 31;
    int g = l >> 2, c = l & 3;
    int wm = w >> 1, wn = w & 1;            // warp grid 2(M) x 2(N), warp tile 64x64

    int e = blockIdx.z;
    int M, rowbase;
    if (cnt) { M = cnt[e]; rowbase = offs[e]; }
    else     { M = Mfixed; rowbase = 0; }
    const float* B = Bb + (long)e * strideB;
    const float* bias = biasb + (long)e * strideBias;
    int bn = blockIdx.x * (FUSED ? 64 : 128);

    // B loader: warp w owns k-row (w + i*4), lane n4 fixed
    int bl_k = tid >> 5;
    int n4 = l << 2;
    int gcolB;
    if (FUSED) {
        int grp = n4 >> 4, sub = n4 & 15;
        gcolB = bn + grp * 8 + sub + (sub >= 8 ? (W - 8) : 0);
    } else {
        gcolB = bn + n4;
    }
    // A smem store swizzle constant for this thread (row = tid)
    int aswz = (tid & 7) << 2;

    int T = K / BK;

    for (int bm = blockIdx.y * BM; bm < M; bm += gridDim.y * BM) {
        int r = bm + tid;
        if (r >= M) r = bm;
        long ga = rowidx ? (long)rowidx[rowbase + r] : (long)(rowbase + r);
        const float* Arow = A + ga * (long)K;

        float acc[4][8][4];
        #pragma unroll
        for (int mt = 0; mt < 4; mt++)
            #pragma unroll
            for (int nt = 0; nt < 8; nt++)
                #pragma unroll
                for (int i = 0; i < 4; i++) acc[mt][nt][i] = 0.f;

        // prologue: stage 0 loads
        {
            uint32_t dA = sb + (uint32_t)((tid * 32) * 4);
            #pragma unroll
            for (int j = 0; j < 8; j++)
                cpa16(dA + (uint32_t)((( (j << 2) ^ aswz)) * 4), Arow + (j << 2));
            #pragma unroll
            for (int i = 0; i < 8; i++) {
                int k = bl_k + i * 4;
                cpa16(sb + (uint32_t)((4096 + swzB(k, n4)) * 4),
                      B + (long)k * N + gcolB);
            }
        }
        CPA_COMMIT();

        for (int it = 0; it < T; it++) {
            CPA_WAIT0();
            __syncthreads();
            if (it + 1 < T) {
                int kg = (it + 1) * BK;
                uint32_t base = sb + (uint32_t)(((it + 1) & 1) * STAGE_W * 4);
                uint32_t dA = base + (uint32_t)((tid * 32) * 4);
                #pragma unroll
                for (int j = 0; j < 8; j++)
                    cpa16(dA + (uint32_t)(((( j << 2) ^ aswz)) * 4), Arow + kg + (j << 2));
                #pragma unroll
                for (int i = 0; i < 8; i++) {
                    int k = bl_k + i * 4;
                    cpa16(base + (uint32_t)((4096 + swzB(k, n4)) * 4),
                          B + (long)(kg + k) * N + gcolB);
                }
            }
            CPA_COMMIT();

            const float* As = sm + (it & 1) * STAGE_W;
            const float* Bs = As + 4096;
            #pragma unroll
            for (int ks = 0; ks < 4; ks++) {
                int kk = ks * 8;
                uint32_t af[4][4], bf[8][2];
                int kc = (kk + c) ^ (g << 2);
                int kc4 = (kk + c + 4) ^ (g << 2);
                #pragma unroll
                for (int mt = 0; mt < 4; mt++) {
                    int rm = wm * 64 + mt * 16 + g;
                    af[mt][0] = f2tf32(As[rm * 32 + kc]);
                    af[mt][1] = f2tf32(As[(rm + 8) * 32 + kc]);
                    af[mt][2] = f2tf32(As[rm * 32 + kc4]);
                    af[mt][3] = f2tf32(As[(rm + 8) * 32 + kc4]);
                }
                #pragma unroll
                for (int nt = 0; nt < 8; nt++) {
                    int cn = (wn * 64 + nt * 8 + g) ^ (c << 3);
                    bf[nt][0] = f2tf32(Bs[(kk + c) * 128 + cn]);
                    bf[nt][1] = f2tf32(Bs[(kk + c + 4) * 128 + cn]);
                }
                #pragma unroll
                for (int mt = 0; mt < 4; mt++)
                    #pragma unroll
                    for (int nt = 0; nt < 8; nt++)
                        mma_tf32(acc[mt][nt], af[mt], bf[nt]);
            }
        }

        // ---- epilogue ----
        if (FUSED) {
            #pragma unroll
            for (int mt = 0; mt < 4; mt++) {
                int rm0 = bm + wm * 64 + mt * 16 + g;
                #pragma unroll
                for (int np = 0; np < 4; np++) {
                    int j0 = bn + (wn * 4 + np) * 8 + 2 * c;
                    float2 ba = *(const float2*)(bias + j0);
                    float2 bg = *(const float2*)(bias + W + j0);
                    float* a = acc[mt][2 * np];
                    float* gt = acc[mt][2 * np + 1];
                    if (rm0 < M) {
                        float2 o;
                        o.x = (a[0] + ba.x) * gelu_exact(gt[0] + bg.x);
                        o.y = (a[1] + ba.y) * gelu_exact(gt[1] + bg.y);
                        *(float2*)(C + (long)(rowbase + rm0) * W + j0) = o;
                    }
                    if (rm0 + 8 < M) {
                        float2 o;
                        o.x = (a[2] + ba.x) * gelu_exact(gt[2] + bg.x);
                        o.y = (a[3] + ba.y) * gelu_exact(gt[3] + bg.y);
                        *(float2*)(C + (long)(rowbase + rm0 + 8) * W + j0) = o;
                    }
                }
            }
        } else {
            #pragma unroll
            for (int mt = 0; mt < 4; mt++) {
                int rm0 = bm + wm * 64 + mt * 16 + g;
                #pragma unroll
                for (int nt = 0; nt < 8; nt++) {
                    int col = bn + wn * 64 + nt * 8 + 2 * c;
                    float2 bv = *(const float2*)(bias + col);
                    if (rm0 < M) {
                        float2 o;
                        o.x = acc[mt][nt][0] + bv.x;
                        o.y = acc[mt][nt][1] + bv.y;
                        *(float2*)(C + (long)(rowbase + rm0) * W + col) = o;
                    }
                    if (rm0 + 8 < M) {
                        float2 o;
                        o.x = acc[mt][nt][2] + bv.x;
                        o.y = acc[mt][nt][3] + bv.y;
                        *(float2*)(C + (long)(rowbase + rm0 + 8) * W + col) = o;
                    }
                }
            }
        }
        __syncthreads();   // protect smem before next bm-tile prologue
    }
}

// ---------------- combine ----------------
__global__ void combine_kernel(const float* __restrict__ ys,
                               const float* __restrict__ yE,
                               float* __restrict__ out) {
    int idx = blockIdx.x * blockDim.x + threadIdx.x;
    int n = idx >> 8;
    int d4 = (idx & 255) << 2;
    int s0 = g_slot[n * 2 + 0], s1 = g_slot[n * 2 + 1];
    float w0 = g_w[n * 2 + 0], w1 = g_w[n * 2 + 1];
    float4 a = *(const float4*)(ys + (long)n * Dm + d4);
    float4 b = *(const float4*)(yE + (long)s0 * Dm + d4);
    float4 cc = *(const float4*)(yE + (long)s1 * Dm + d4);
    float4 o;
    o.x = a.x + w0 * b.x + w1 * cc.x;
    o.y = a.y + w0 * b.y + w1 * cc.y;
    o.z = a.z + w0 * b.z + w1 * cc.z;
    o.w = a.w + w0 * b.w + w1 * cc.w;
    *(float4*)(out + (long)n * Dm + d4) = o;
}

// ---------------- launch ----------------
extern "C" void kernel_launch(void* const* d_in, const int* in_sizes, int n_in,
                              void* d_out, int out_size) {
    const float* x   = (const float*)d_in[0];
    const float* Ws1 = (const float*)d_in[1];
    const float* bs1 = (const float*)d_in[2];
    const float* Ws2 = (const float*)d_in[3];
    const float* bs2 = (const float*)d_in[4];
    const float* We1 = (const float*)d_in[5];
    const float* be1 = (const float*)d_in[6];
    const float* We2 = (const float*)d_in[7];
    const float* be2 = (const float*)d_in[8];
    const float* Wr  = (const float*)d_in[9];
    const float* br  = (const float*)d_in[10];
    float* out = (float*)d_out;

    float *pAact, *pys, *pAr, *pyE;
    int *pcnt, *poffs, *ptok;
    cudaGetSymbolAddress((void**)&pAact, g_Aact);
    cudaGetSymbolAddress((void**)&pys,   g_ys);
    cudaGetSymbolAddress((void**)&pAr,   g_Ar);
    cudaGetSymbolAddress((void**)&pyE,   g_yE);
    cudaGetSymbolAddress((void**)&pcnt,  g_cnt);
    cudaGetSymbolAddress((void**)&poffs, g_offs);
    cudaGetSymbolAddress((void**)&ptok,  g_tokrow);

    cudaFuncSetAttribute(tf32gemm<true>,  cudaFuncAttributeMaxDynamicSharedMemorySize, GEMM_SMEM_BYTES);
    cudaFuncSetAttribute(tf32gemm<false>, cudaFuncAttributeMaxDynamicSharedMemorySize, GEMM_SMEM_BYTES);

    // 1) routing
    router_kernel<<<Nt, 128>>>(x, Wr, br);
    dispatch_kernel<<<1, 1024>>>();

    // 2) GEMM1 (fused GEGLU): shared then routed
    tf32gemm<true><<<dim3(HSdim / 64, Nt / BM, 1), 128, GEMM_SMEM_BYTES>>>(
        x, Ws1, bs1, pAact, Nt, 2 * HSdim, HSdim, Dm,
        nullptr, nullptr, nullptr, 0, 0);
    tf32gemm<true><<<dim3(HRdim / 64, 3, Ne), 128, GEMM_SMEM_BYTES>>>(
        x, We1, be1, pAr, 0, 2 * HRdim, HRdim, Dm,
        pcnt, poffs, ptok, (long)Dm * 2 * HRdim, 2 * HRdim);

    // 3) GEMM2: shared then routed
    tf32gemm<false><<<dim3(Dm / 128, Nt / BM, 1), 128, GEMM_SMEM_BYTES>>>(
        pAact, Ws2, bs2, pys, Nt, Dm, Dm, HSdim,
        nullptr, nullptr, nullptr, 0, 0);
    tf32gemm<false><<<dim3(Dm / 128, 5, Ne), 128, GEMM_SMEM_BYTES>>>(
        pAr, We2, be2, pyE, 0, Dm, Dm, HRdim,
        pcnt, poffs, nullptr, (long)HRdim * Dm, Dm);

    // 4) combine
    combine_kernel<<<(Nt * Dm / 4) / 256, 256>>>(pys, pyE, out);
}

// round 12
// speedup vs baseline: 1.0664x; 1.0015x over previous
#include <cuda_runtime.h>
#include <math.h>
#include <cstdint>

#define Dm 1024
#define Ne 12
#define Nt 2048
#define HSdim 2048
#define HRdim 3072
#define TAUf 1.5f

// ---------------- scratch ----------------
__device__ float g_Aact[(long)Nt * HSdim];
__device__ float g_ys[(long)Nt * Dm];
__device__ float g_Ar[(long)2 * Nt * HRdim];
__device__ float g_yE[(long)2 * Nt * Dm];
__device__ int   g_top[Nt * 2];
__device__ float g_w[Nt * 2];
__device__ int   g_cnt[Ne];
__device__ int   g_offs[Ne + 1];
__device__ int   g_tokrow[2 * Nt];
__device__ int   g_slot[Nt * 2];

// ---------------- helpers ----------------
__device__ __forceinline__ uint32_t smem_u32(const void* p) {
    uint32_t a;
    asm("{ .reg .u64 t; cvta.to.shared.u64 t, %1; cvt.u32.u64 %0, t; }" : "=r"(a) : "l"(p));
    return a;
}
__device__ __forceinline__ uint32_t f2tf32(float x) {
    uint32_t r;
    asm("cvt.rna.tf32.f32 %0, %1;" : "=r"(r) : "f"(x));
    return r;
}
__device__ __forceinline__ void mma_tf32(float* d, const uint32_t* a, const uint32_t* b) {
    asm volatile(
        "mma.sync.aligned.m16n8k8.row.col.f32.tf32.tf32.f32 "
        "{%0,%1,%2,%3}, {%4,%5,%6,%7}, {%8,%9}, {%0,%1,%2,%3};"
        : "+f"(d[0]), "+f"(d[1]), "+f"(d[2]), "+f"(d[3])
        : "r"(a[0]), "r"(a[1]), "r"(a[2]), "r"(a[3]), "r"(b[0]), "r"(b[1]));
}
__device__ __forceinline__ void cpa16(uint32_t dst, const void* src) {
    asm volatile("cp.async.cg.shared.global [%0], [%1], 16;" :: "r"(dst), "l"(src));
}
#define CPA_COMMIT() asm volatile("cp.async.commit_group;" ::: "memory")
#define CPA_WAIT1()  asm volatile("cp.async.wait_group 1;" ::: "memory")
__device__ __forceinline__ float gelu_exact(float g) {
    return 0.5f * g * (1.0f + erff(g * 0.70710678118654752f));
}
__device__ __forceinline__ int swzB(int k, int n) { return k * 128 + (n ^ ((k & 3) << 3)); }

// ---------------- routing ----------------
__global__ void router_kernel(const float* __restrict__ x,
                              const float* __restrict__ Wr,
                              const float* __restrict__ br) {
    int n = blockIdx.x;
    __shared__ float sx[Dm];
    __shared__ float slog[Ne];
    for (int k = threadIdx.x; k < Dm; k += blockDim.x) sx[k] = x[(long)n * Dm + k];
    __syncthreads();
    int e = threadIdx.x;
    if (e < Ne) {
        float s = 0.f;
        #pragma unroll 8
        for (int k = 0; k < Dm; k++) s += sx[k] * Wr[k * Ne + e];
        slog[e] = (s + br[e]) / TAUf;
    }
    __syncthreads();
    if (threadIdx.x == 0) {
        int i0 = 0; float v0 = slog[0];
        for (int j = 1; j < Ne; j++) if (slog[j] > v0) { v0 = slog[j]; i0 = j; }
        int i1 = -1; float v1 = -1e30f;
        for (int j = 0; j < Ne; j++) if (j != i0 && slog[j] > v1) { v1 = slog[j]; i1 = j; }
        float e1 = expf(v1 - v0);
        float z = 1.0f + e1;
        g_top[n * 2 + 0] = i0; g_top[n * 2 + 1] = i1;
        g_w[n * 2 + 0] = 1.0f / z; g_w[n * 2 + 1] = e1 / z;
    }
}

__global__ void __launch_bounds__(1024) dispatch_kernel() {
    __shared__ int scnt[Ne], soffs[Ne];
    int tid = threadIdx.x;
    if (tid < Ne) scnt[tid] = 0;
    __syncthreads();
    int rnk[4], eid[4];
    #pragma unroll
    for (int it = 0; it < 4; it++) {
        int i = tid + it * 1024;
        eid[it] = g_top[i];
        rnk[it] = atomicAdd(&scnt[eid[it]], 1);
    }
    __syncthreads();
    if (tid == 0) {
        int o = 0;
        for (int e2 = 0; e2 < Ne; e2++) { soffs[e2] = o; o += scnt[e2]; }
    }
    __syncthreads();
    #pragma unroll
    for (int it = 0; it < 4; it++) {
        int i = tid + it * 1024;
        int r = soffs[eid[it]] + rnk[it];
        g_tokrow[r] = i >> 1;
        g_slot[i] = r;
    }
    if (tid < Ne) { g_cnt[tid] = scnt[tid]; g_offs[tid] = soffs[tid]; }
    if (tid == 0) g_offs[Ne] = 2 * Nt;
}

// ---------------- TF32 mma.sync GEMM, cp.async 3-stage, 64x64 warp tiles ----------------
// CTA tile 128x128x32. 128 threads = 4 warps (2x2). Stage = A(4096w) + B(4096w).
#define BM 128
#define BK 32
#define STAGE_W 8192
#define NSTAGE 3
#define GEMM_SMEM_BYTES (NSTAGE * STAGE_W * 4)   // 98304

template <bool FUSED>
__global__ void __launch_bounds__(128, 2)
tf32gemm(const float* __restrict__ A,
         const float* __restrict__ Bb,
         const float* __restrict__ biasb,
         float* __restrict__ C,
         int Mfixed, int N, int W, int K,
         const int* __restrict__ cnt,
         const int* __restrict__ offs,
         const int* __restrict__ rowidx,
         long strideB, int strideBias) {
    extern __shared__ float sm[];
    uint32_t sb = smem_u32(sm);

    int tid = threadIdx.x;
    int w = tid >> 5, l = tid & 31;
    int g = l >> 2, c = l & 3;
    int wm = w >> 1, wn = w & 1;            // warp grid 2(M) x 2(N), warp tile 64x64

    int e = blockIdx.z;
    int M, rowbase;
    if (cnt) { M = cnt[e]; rowbase = offs[e]; }
    else     { M = Mfixed; rowbase = 0; }
    const float* B = Bb + (long)e * strideB;
    const float* bias = biasb + (long)e * strideBias;
    int bn = blockIdx.x * (FUSED ? 64 : 128);

    // B loader: warp w owns k-row (w + i*4), lane n4 fixed
    int bl_k = tid >> 5;
    int n4 = l << 2;
    int gcolB;
    if (FUSED) {
        int grp = n4 >> 4, sub = n4 & 15;
        gcolB = bn + grp * 8 + sub + (sub >= 8 ? (W - 8) : 0);
    } else {
        gcolB = bn + n4;
    }
    int aswz = (tid & 7) << 2;
    int T = K / BK;

    for (int bm = blockIdx.y * BM; bm < M; bm += gridDim.y * BM) {
        int r = bm + tid;
        if (r >= M) r = bm;
        long ga = rowidx ? (long)rowidx[rowbase + r] : (long)(rowbase + r);
        const float* Arow = A + ga * (long)K;

        auto issue_stage = [&](int itg) {
            int kg = itg * BK;
            uint32_t base = sb + (uint32_t)((itg % NSTAGE) * STAGE_W * 4);
            uint32_t dA = base + (uint32_t)((tid * 32) * 4);
            #pragma unroll
            for (int j = 0; j < 8; j++)
                cpa16(dA + (uint32_t)((((j << 2) ^ aswz)) * 4), Arow + kg + (j << 2));
            #pragma unroll
            for (int i = 0; i < 8; i++) {
                int k = bl_k + i * 4;
                cpa16(base + (uint32_t)((4096 + swzB(k, n4)) * 4),
                      B + (long)(kg + k) * N + gcolB);
            }
        };

        float acc[4][8][4];
        #pragma unroll
        for (int mt = 0; mt < 4; mt++)
            #pragma unroll
            for (int nt = 0; nt < 8; nt++)
                #pragma unroll
                for (int i = 0; i < 4; i++) acc[mt][nt][i] = 0.f;

        // prologue: stages 0 and 1 in flight
        issue_stage(0);
        CPA_COMMIT();
        if (T > 1) issue_stage(1);
        CPA_COMMIT();

        for (int it = 0; it < T; it++) {
            CPA_WAIT1();          // G(it) complete (G(it+1) may remain in flight)
            __syncthreads();      // visibility of all threads' loads; buf (it+2)%3 free
            if (it + 2 < T) issue_stage(it + 2);
            CPA_COMMIT();

            const float* As = sm + (it % NSTAGE) * STAGE_W;
            const float* Bs = As + 4096;
            #pragma unroll
            for (int ks = 0; ks < 4; ks++) {
                int kk = ks * 8;
                uint32_t af[4][4], bf[8][2];
                int kc = (kk + c) ^ (g << 2);
                int kc4 = (kk + c + 4) ^ (g << 2);
                #pragma unroll
                for (int mt = 0; mt < 4; mt++) {
                    int rm = wm * 64 + mt * 16 + g;
                    af[mt][0] = f2tf32(As[rm * 32 + kc]);
                    af[mt][1] = f2tf32(As[(rm + 8) * 32 + kc]);
                    af[mt][2] = f2tf32(As[rm * 32 + kc4]);
                    af[mt][3] = f2tf32(As[(rm + 8) * 32 + kc4]);
                }
                #pragma unroll
                for (int nt = 0; nt < 8; nt++) {
                    int cn = (wn * 64 + nt * 8 + g) ^ (c << 3);
                    bf[nt][0] = f2tf32(Bs[(kk + c) * 128 + cn]);
                    bf[nt][1] = f2tf32(Bs[(kk + c + 4) * 128 + cn]);
                }
                #pragma unroll
                for (int mt = 0; mt < 4; mt++)
                    #pragma unroll
                    for (int nt = 0; nt < 8; nt++)
                        mma_tf32(acc[mt][nt], af[mt], bf[nt]);
            }
        }

        // ---- epilogue ----
        if (FUSED) {
            #pragma unroll
            for (int mt = 0; mt < 4; mt++) {
                int rm0 = bm + wm * 64 + mt * 16 + g;
                #pragma unroll
                for (int np = 0; np < 4; np++) {
                    int j0 = bn + (wn * 4 + np) * 8 + 2 * c;
                    float2 ba = *(const float2*)(bias + j0);
                    float2 bg = *(const float2*)(bias + W + j0);
                    float* a = acc[mt][2 * np];
                    float* gt = acc[mt][2 * np + 1];
                    if (rm0 < M) {
                        float2 o;
                        o.x = (a[0] + ba.x) * gelu_exact(gt[0] + bg.x);
                        o.y = (a[1] + ba.y) * gelu_exact(gt[1] + bg.y);
                        *(float2*)(C + (long)(rowbase + rm0) * W + j0) = o;
                    }
                    if (rm0 + 8 < M) {
                        float2 o;
                        o.x = (a[2] + ba.x) * gelu_exact(gt[2] + bg.x);
                        o.y = (a[3] + ba.y) * gelu_exact(gt[3] + bg.y);
                        *(float2*)(C + (long)(rowbase + rm0 + 8) * W + j0) = o;
                    }
                }
            }
        } else {
            #pragma unroll
            for (int mt = 0; mt < 4; mt++) {
                int rm0 = bm + wm * 64 + mt * 16 + g;
                #pragma unroll
                for (int nt = 0; nt < 8; nt++) {
                    int col = bn + wn * 64 + nt * 8 + 2 * c;
                    float2 bv = *(const float2*)(bias + col);
                    if (rm0 < M) {
                        float2 o;
                        o.x = acc[mt][nt][0] + bv.x;
                        o.y = acc[mt][nt][1] + bv.y;
                        *(float2*)(C + (long)(rowbase + rm0) * W + col) = o;
                    }
                    if (rm0 + 8 < M) {
                        float2 o;
                        o.x = acc[mt][nt][2] + bv.x;
                        o.y = acc[mt][nt][3] + bv.y;
                        *(float2*)(C + (long)(rowbase + rm0 + 8) * W + col) = o;
                    }
                }
            }
        }
        __syncthreads();   // smem safe before next bm-tile prologue
    }
}

// ---------------- combine ----------------
__global__ void combine_kernel(const float* __restrict__ ys,
                               const float* __restrict__ yE,
                               float* __restrict__ out) {
    int idx = blockIdx.x * blockDim.x + threadIdx.x;
    int n = idx >> 8;
    int d4 = (idx & 255) << 2;
    int s0 = g_slot[n * 2 + 0], s1 = g_slot[n * 2 + 1];
    float w0 = g_w[n * 2 + 0], w1 = g_w[n * 2 + 1];
    float4 a = *(const float4*)(ys + (long)n * Dm + d4);
    float4 b = *(const float4*)(yE + (long)s0 * Dm + d4);
    float4 cc = *(const float4*)(yE + (long)s1 * Dm + d4);
    float4 o;
    o.x = a.x + w0 * b.x + w1 * cc.x;
    o.y = a.y + w0 * b.y + w1 * cc.y;
    o.z = a.z + w0 * b.z + w1 * cc.z;
    o.w = a.w + w0 * b.w + w1 * cc.w;
    *(float4*)(out + (long)n * Dm + d4) = o;
}

// ---------------- launch ----------------
extern "C" void kernel_launch(void* const* d_in, const int* in_sizes, int n_in,
                              void* d_out, int out_size) {
    const float* x   = (const float*)d_in[0];
    const float* Ws1 = (const float*)d_in[1];
    const float* bs1 = (const float*)d_in[2];
    const float* Ws2 = (const float*)d_in[3];
    const float* bs2 = (const float*)d_in[4];
    const float* We1 = (const float*)d_in[5];
    const float* be1 = (const float*)d_in[6];
    const float* We2 = (const float*)d_in[7];
    const float* be2 = (const float*)d_in[8];
    const float* Wr  = (const float*)d_in[9];
    const float* br  = (const float*)d_in[10];
    float* out = (float*)d_out;

    float *pAact, *pys, *pAr, *pyE;
    int *pcnt, *poffs, *ptok;
    cudaGetSymbolAddress((void**)&pAact, g_Aact);
    cudaGetSymbolAddress((void**)&pys,   g_ys);
    cudaGetSymbolAddress((void**)&pAr,   g_Ar);
    cudaGetSymbolAddress((void**)&pyE,   g_yE);
    cudaGetSymbolAddress((void**)&pcnt,  g_cnt);
    cudaGetSymbolAddress((void**)&poffs, g_offs);
    cudaGetSymbolAddress((void**)&ptok,  g_tokrow);

    cudaFuncSetAttribute(tf32gemm<true>,  cudaFuncAttributeMaxDynamicSharedMemorySize, GEMM_SMEM_BYTES);
    cudaFuncSetAttribute(tf32gemm<false>, cudaFuncAttributeMaxDynamicSharedMemorySize, GEMM_SMEM_BYTES);

    // 1) routing
    router_kernel<<<Nt, 128>>>(x, Wr, br);
    dispatch_kernel<<<1, 1024>>>();

    // 2) GEMM1 (fused GEGLU): shared then routed
    tf32gemm<true><<<dim3(HSdim / 64, Nt / BM, 1), 128, GEMM_SMEM_BYTES>>>(
        x, Ws1, bs1, pAact, Nt, 2 * HSdim, HSdim, Dm,
        nullptr, nullptr, nullptr, 0, 0);
    tf32gemm<true><<<dim3(HRdim / 64, 4, Ne), 128, GEMM_SMEM_BYTES>>>(
        x, We1, be1, pAr, 0, 2 * HRdim, HRdim, Dm,
        pcnt, poffs, ptok, (long)Dm * 2 * HRdim, 2 * HRdim);

    // 3) GEMM2: shared then routed
    tf32gemm<false><<<dim3(Dm / 128, Nt / BM, 1), 128, GEMM_SMEM_BYTES>>>(
        pAact, Ws2, bs2, pys, Nt, Dm, Dm, HSdim,
        nullptr, nullptr, nullptr, 0, 0);
    tf32gemm<false><<<dim3(Dm / 128, 5, Ne), 128, GEMM_SMEM_BYTES>>>(
        pAr, We2, be2, pyE, 0, Dm, Dm, HRdim,
        pcnt, poffs, nullptr, (long)HRdim * Dm, Dm);

    // 4) combine
    combine_kernel<<<(Nt * Dm / 4) / 256, 256>>>(pys, pyE, out);
}

// round 15
// speedup vs baseline: 1.2673x; 1.1883x over previous
#include <cuda_runtime.h>
#include <math.h>
#include <cstdint>

#define Dm 1024
#define Ne 12
#define Nt 2048
#define HSdim 2048
#define HRdim 3072
#define TAUf 1.5f

// ---------------- scratch ----------------
__device__ float g_Aact[(long)Nt * HSdim];
__device__ float g_ys[(long)Nt * Dm];
__device__ float g_Ar[(long)2 * Nt * HRdim];
__device__ float g_yE[(long)2 * Nt * Dm];
__device__ int   g_top[Nt * 2];
__device__ float g_w[Nt * 2];
__device__ int   g_cnt[Ne];
__device__ int   g_offs[Ne + 1];
__device__ int   g_tokrow[2 * Nt];
__device__ int   g_slot[Nt * 2];

// ---------------- helpers ----------------
__device__ __forceinline__ uint32_t smem_u32(const void* p) {
    uint32_t a;
    asm("{ .reg .u64 t; cvta.to.shared.u64 t, %1; cvt.u32.u64 %0, t; }" : "=r"(a) : "l"(p));
    return a;
}
__device__ __forceinline__ uint32_t f2tf32(float x) {
    uint32_t r;
    asm("cvt.rna.tf32.f32 %0, %1;" : "=r"(r) : "f"(x));
    return r;
}
__device__ __forceinline__ void mma_tf32(float* d, const uint32_t* a, const uint32_t* b) {
    asm volatile(
        "mma.sync.aligned.m16n8k8.row.col.f32.tf32.tf32.f32 "
        "{%0,%1,%2,%3}, {%4,%5,%6,%7}, {%8,%9}, {%0,%1,%2,%3};"
        : "+f"(d[0]), "+f"(d[1]), "+f"(d[2]), "+f"(d[3])
        : "r"(a[0]), "r"(a[1]), "r"(a[2]), "r"(a[3]), "r"(b[0]), "r"(b[1]));
}
__device__ __forceinline__ void cpa16(uint32_t dst, const void* src) {
    asm volatile("cp.async.cg.shared.global [%0], [%1], 16;" :: "r"(dst), "l"(src));
}
#define CPA_COMMIT() asm volatile("cp.async.commit_group;" ::: "memory")
#define CPA_WAIT1()  asm volatile("cp.async.wait_group 1;" ::: "memory")
__device__ __forceinline__ float gelu_exact(float g) {
    return 0.5f * g * (1.0f + erff(g * 0.70710678118654752f));
}
__device__ __forceinline__ int swzB(int k, int n) { return k * 128 + (n ^ ((k & 3) << 3)); }

// ---------------- routing ----------------
__global__ void router_kernel(const float* __restrict__ x,
                              const float* __restrict__ Wr,
                              const float* __restrict__ br) {
    int n = blockIdx.x;
    __shared__ float sx[Dm];
    __shared__ float slog[Ne];
    for (int k = threadIdx.x; k < Dm; k += blockDim.x) sx[k] = x[(long)n * Dm + k];
    __syncthreads();
    int e = threadIdx.x;
    if (e < Ne) {
        float s = 0.f;
        #pragma unroll 8
        for (int k = 0; k < Dm; k++) s += sx[k] * Wr[k * Ne + e];
        slog[e] = (s + br[e]) / TAUf;
    }
    __syncthreads();
    if (threadIdx.x == 0) {
        int i0 = 0; float v0 = slog[0];
        for (int j = 1; j < Ne; j++) if (slog[j] > v0) { v0 = slog[j]; i0 = j; }
        int i1 = -1; float v1 = -1e30f;
        for (int j = 0; j < Ne; j++) if (j != i0 && slog[j] > v1) { v1 = slog[j]; i1 = j; }
        float e1 = expf(v1 - v0);
        float z = 1.0f + e1;
        g_top[n * 2 + 0] = i0; g_top[n * 2 + 1] = i1;
        g_w[n * 2 + 0] = 1.0f / z; g_w[n * 2 + 1] = e1 / z;
    }
}

__global__ void __launch_bounds__(1024) dispatch_kernel() {
    __shared__ int scnt[Ne], soffs[Ne];
    int tid = threadIdx.x;
    if (tid < Ne) scnt[tid] = 0;
    __syncthreads();
    int rnk[4], eid[4];
    #pragma unroll
    for (int it = 0; it < 4; it++) {
        int i = tid + it * 1024;
        eid[it] = g_top[i];
        rnk[it] = atomicAdd(&scnt[eid[it]], 1);
    }
    __syncthreads();
    if (tid == 0) {
        int o = 0;
        for (int e2 = 0; e2 < Ne; e2++) { soffs[e2] = o; o += scnt[e2]; }
    }
    __syncthreads();
    #pragma unroll
    for (int it = 0; it < 4; it++) {
        int i = tid + it * 1024;
        int r = soffs[eid[it]] + rnk[it];
        g_tokrow[r] = i >> 1;
        g_slot[i] = r;
    }
    if (tid < Ne) { g_cnt[tid] = scnt[tid]; g_offs[tid] = soffs[tid]; }
    if (tid == 0) g_offs[Ne] = 2 * Nt;
}

// ---------------- TF32 mma.sync GEMM, cp.async 3-stage ----------------
// CTA tile 128x128x32. 256 threads = 8 warps (2M x 4N), warp tile 64x32.
// Regs capped at 128 (launch_bounds 256,2) -> 16 warps/SM.
#define BM 128
#define BK 32
#define STAGE_W 8192
#define NSTAGE 3
#define GEMM_SMEM_BYTES (NSTAGE * STAGE_W * 4)   // 98304

template <bool FUSED>
__global__ void __launch_bounds__(256, 2)
tf32gemm(const float* __restrict__ A,
         const float* __restrict__ Bb,
         const float* __restrict__ biasb,
         float* __restrict__ C,
         int Mfixed, int N, int W, int K,
         const int* __restrict__ cnt,
         const int* __restrict__ offs,
         const int* __restrict__ rowidx,
         long strideB, int strideBias) {
    extern __shared__ float sm[];
    uint32_t sb = smem_u32(sm);

    int tid = threadIdx.x;
    int w = tid >> 5, l = tid & 31;
    int g = l >> 2, c = l & 3;
    int wm = w >> 2, wn = w & 3;            // warp grid 2(M) x 4(N), warp tile 64x32

    int e = blockIdx.z;
    int M, rowbase;
    if (cnt) { M = cnt[e]; rowbase = offs[e]; }
    else     { M = Mfixed; rowbase = 0; }
    const float* B = Bb + (long)e * strideB;
    const float* bias = biasb + (long)e * strideBias;
    int bn = blockIdx.x * (FUSED ? 64 : 128);

    // A loader: thread -> row am2, k-half ak (16 words), 4 chunks
    int am2 = tid >> 1;
    int ak = (tid & 1) << 4;
    int aswz = (am2 & 7) << 2;
    // B loader: thread -> k-row bk, chunks (bc + i*8)*4 words, 4 chunks
    int bk = tid >> 3;
    int bc = tid & 7;
    int gcolB[4];
    #pragma unroll
    for (int i = 0; i < 4; i++) {
        int n4 = (bc + i * 8) << 2;
        if (FUSED) {
            int grp = n4 >> 4, sub = n4 & 15;
            gcolB[i] = bn + grp * 8 + sub + (sub >= 8 ? (W - 8) : 0);
        } else {
            gcolB[i] = bn + n4;
        }
    }
    int T = K / BK;

    for (int bm = blockIdx.y * BM; bm < M; bm += gridDim.y * BM) {
        int r = bm + am2;
        if (r >= M) r = bm;
        long ga = rowidx ? (long)rowidx[rowbase + r] : (long)(rowbase + r);
        const float* Arow = A + ga * (long)K;

        auto issue_stage = [&](int itg) {
            int kg = itg * BK;
            uint32_t base = sb + (uint32_t)((itg % NSTAGE) * STAGE_W * 4);
            uint32_t dA = base + (uint32_t)((am2 * 32) * 4);
            #pragma unroll
            for (int j = 0; j < 4; j++) {
                int kw = ak + (j << 2);
                cpa16(dA + (uint32_t)((kw ^ aswz) * 4), Arow + kg + kw);
            }
            #pragma unroll
            for (int i = 0; i < 4; i++) {
                int n4 = (bc + i * 8) << 2;
                cpa16(base + (uint32_t)((4096 + swzB(bk, n4)) * 4),
                      B + (long)(kg + bk) * N + gcolB[i]);
            }
        };

        float acc[4][4][4];
        #pragma unroll
        for (int mt = 0; mt < 4; mt++)
            #pragma unroll
            for (int nt = 0; nt < 4; nt++)
                #pragma unroll
                for (int i = 0; i < 4; i++) acc[mt][nt][i] = 0.f;

        issue_stage(0);
        CPA_COMMIT();
        if (T > 1) issue_stage(1);
        CPA_COMMIT();

        for (int it = 0; it < T; it++) {
            CPA_WAIT1();
            __syncthreads();
            if (it + 2 < T) issue_stage(it + 2);
            CPA_COMMIT();

            const float* As = sm + (it % NSTAGE) * STAGE_W;
            const float* Bs = As + 4096;
            #pragma unroll
            for (int ks = 0; ks < 4; ks++) {
                int kk = ks * 8;
                uint32_t af[4][4], bf[4][2];
                int kc = (kk + c) ^ (g << 2);
                int kc4 = (kk + c + 4) ^ (g << 2);
                #pragma unroll
                for (int mt = 0; mt < 4; mt++) {
                    int rm = wm * 64 + mt * 16 + g;
                    af[mt][0] = f2tf32(As[rm * 32 + kc]);
                    af[mt][1] = f2tf32(As[(rm + 8) * 32 + kc]);
                    af[mt][2] = f2tf32(As[rm * 32 + kc4]);
                    af[mt][3] = f2tf32(As[(rm + 8) * 32 + kc4]);
                }
                #pragma unroll
                for (int nt = 0; nt < 4; nt++) {
                    int cn = (wn * 32 + nt * 8 + g) ^ (c << 3);
                    bf[nt][0] = f2tf32(Bs[(kk + c) * 128 + cn]);
                    bf[nt][1] = f2tf32(Bs[(kk + c + 4) * 128 + cn]);
                }
                #pragma unroll
                for (int mt = 0; mt < 4; mt++)
                    #pragma unroll
                    for (int nt = 0; nt < 4; nt++)
                        mma_tf32(acc[mt][nt], af[mt], bf[nt]);
            }
        }

        // ---- epilogue ----
        if (FUSED) {
            #pragma unroll
            for (int mt = 0; mt < 4; mt++) {
                int rm0 = bm + wm * 64 + mt * 16 + g;
                #pragma unroll
                for (int np = 0; np < 2; np++) {
                    int j0 = bn + (wn * 2 + np) * 8 + 2 * c;
                    float2 ba = *(const float2*)(bias + j0);
                    float2 bg = *(const float2*)(bias + W + j0);
                    float* a = acc[mt][2 * np];
                    float* gt = acc[mt][2 * np + 1];
                    if (rm0 < M) {
                        float2 o;
                        o.x = (a[0] + ba.x) * gelu_exact(gt[0] + bg.x);
                        o.y = (a[1] + ba.y) * gelu_exact(gt[1] + bg.y);
                        *(float2*)(C + (long)(rowbase + rm0) * W + j0) = o;
                    }
                    if (rm0 + 8 < M) {
                        float2 o;
                        o.x = (a[2] + ba.x) * gelu_exact(gt[2] + bg.x);
                        o.y = (a[3] + ba.y) * gelu_exact(gt[3] + bg.y);
                        *(float2*)(C + (long)(rowbase + rm0 + 8) * W + j0) = o;
                    }
                }
            }
        } else {
            #pragma unroll
            for (int mt = 0; mt < 4; mt++) {
                int rm0 = bm + wm * 64 + mt * 16 + g;
                #pragma unroll
                for (int nt = 0; nt < 4; nt++) {
                    int col = bn + wn * 32 + nt * 8 + 2 * c;
                    float2 bv = *(const float2*)(bias + col);
                    if (rm0 < M) {
                        float2 o;
                        o.x = acc[mt][nt][0] + bv.x;
                        o.y = acc[mt][nt][1] + bv.y;
                        *(float2*)(C + (long)(rowbase + rm0) * W + col) = o;
                    }
                    if (rm0 + 8 < M) {
                        float2 o;
                        o.x = acc[mt][nt][2] + bv.x;
                        o.y = acc[mt][nt][3] + bv.y;
                        *(float2*)(C + (long)(rowbase + rm0 + 8) * W + col) = o;
                    }
                }
            }
        }
        __syncthreads();
    }
}

// ---------------- combine ----------------
__global__ void combine_kernel(const float* __restrict__ ys,
                               const float* __restrict__ yE,
                               float* __restrict__ out) {
    int idx = blockIdx.x * blockDim.x + threadIdx.x;
    int n = idx >> 8;
    int d4 = (idx & 255) << 2;
    int s0 = g_slot[n * 2 + 0], s1 = g_slot[n * 2 + 1];
    float w0 = g_w[n * 2 + 0], w1 = g_w[n * 2 + 1];
    float4 a = *(const float4*)(ys + (long)n * Dm + d4);
    float4 b = *(const float4*)(yE + (long)s0 * Dm + d4);
    float4 cc = *(const float4*)(yE + (long)s1 * Dm + d4);
    float4 o;
    o.x = a.x + w0 * b.x + w1 * cc.x;
    o.y = a.y + w0 * b.y + w1 * cc.y;
    o.z = a.z + w0 * b.z + w1 * cc.z;
    o.w = a.w + w0 * b.w + w1 * cc.w;
    *(float4*)(out + (long)n * Dm + d4) = o;
}

// ---------------- launch ----------------
extern "C" void kernel_launch(void* const* d_in, const int* in_sizes, int n_in,
                              void* d_out, int out_size) {
    const float* x   = (const float*)d_in[0];
    const float* Ws1 = (const float*)d_in[1];
    const float* bs1 = (const float*)d_in[2];
    const float* Ws2 = (const float*)d_in[3];
    const float* bs2 = (const float*)d_in[4];
    const float* We1 = (const float*)d_in[5];
    const float* be1 = (const float*)d_in[6];
    const float* We2 = (const float*)d_in[7];
    const float* be2 = (const float*)d_in[8];
    const float* Wr  = (const float*)d_in[9];
    const float* br  = (const float*)d_in[10];
    float* out = (float*)d_out;

    float *pAact, *pys, *pAr, *pyE;
    int *pcnt, *poffs, *ptok;
    cudaGetSymbolAddress((void**)&pAact, g_Aact);
    cudaGetSymbolAddress((void**)&pys,   g_ys);
    cudaGetSymbolAddress((void**)&pAr,   g_Ar);
    cudaGetSymbolAddress((void**)&pyE,   g_yE);
    cudaGetSymbolAddress((void**)&pcnt,  g_cnt);
    cudaGetSymbolAddress((void**)&poffs, g_offs);
    cudaGetSymbolAddress((void**)&ptok,  g_tokrow);

    cudaFuncSetAttribute(tf32gemm<true>,  cudaFuncAttributeMaxDynamicSharedMemorySize, GEMM_SMEM_BYTES);
    cudaFuncSetAttribute(tf32gemm<false>, cudaFuncAttributeMaxDynamicSharedMemorySize, GEMM_SMEM_BYTES);

    // 1) routing
    router_kernel<<<Nt, 128>>>(x, Wr, br);
    dispatch_kernel<<<1, 1024>>>();

    // 2) GEMM1 (fused GEGLU): shared then routed
    tf32gemm<true><<<dim3(HSdim / 64, Nt / BM, 1), 256, GEMM_SMEM_BYTES>>>(
        x, Ws1, bs1, pAact, Nt, 2 * HSdim, HSdim, Dm,
        nullptr, nullptr, nullptr, 0, 0);
    tf32gemm<true><<<dim3(HRdim / 64, 4, Ne), 256, GEMM_SMEM_BYTES>>>(
        x, We1, be1, pAr, 0, 2 * HRdim, HRdim, Dm,
        pcnt, poffs, ptok, (long)Dm * 2 * HRdim, 2 * HRdim);

    // 3) GEMM2: shared then routed
    tf32gemm<false><<<dim3(Dm / 128, Nt / BM, 1), 256, GEMM_SMEM_BYTES>>>(
        pAact, Ws2, bs2, pys, Nt, Dm, Dm, HSdim,
        nullptr, nullptr, nullptr, 0, 0);
    tf32gemm<false><<<dim3(Dm / 128, 5, Ne), 256, GEMM_SMEM_BYTES>>>(
        pAr, We2, be2, pyE, 0, Dm, Dm, HRdim,
        pcnt, poffs, nullptr, (long)HRdim * Dm, Dm);

    // 4) combine
    combine_kernel<<<(Nt * Dm / 4) / 256, 256>>>(pys, pyE, out);
}

// round 16
// speedup vs baseline: 1.3321x; 1.0512x over previous
#include <cuda_runtime.h>
#include <math.h>
#include <cstdint>

#define Dm 1024
#define Ne 12
#define Nt 2048
#define HSdim 2048
#define HRdim 3072
#define TAUf 1.5f

// ---------------- scratch ----------------
__device__ float g_xr[(long)Nt * Dm];              // tf32-rounded copy of x
__device__ float g_Aact[(long)Nt * HSdim];
__device__ float g_ys[(long)Nt * Dm];
__device__ float g_Ar[(long)2 * Nt * HRdim];
__device__ float g_yE[(long)2 * Nt * Dm];
__device__ int   g_top[Nt * 2];
__device__ float g_w[Nt * 2];
__device__ int   g_cnt[Ne];
__device__ int   g_offs[Ne + 1];
__device__ int   g_tokrow[2 * Nt];
__device__ int   g_slot[Nt * 2];

// ---------------- helpers ----------------
__device__ __forceinline__ uint32_t smem_u32(const void* p) {
    uint32_t a;
    asm("{ .reg .u64 t; cvta.to.shared.u64 t, %1; cvt.u32.u64 %0, t; }" : "=r"(a) : "l"(p));
    return a;
}
__device__ __forceinline__ uint32_t f2tf32(float x) {
    uint32_t r;
    asm("cvt.rna.tf32.f32 %0, %1;" : "=r"(r) : "f"(x));
    return r;
}
__device__ __forceinline__ float rnd_tf32(float x) { return __uint_as_float(f2tf32(x)); }
__device__ __forceinline__ void mma_tf32(float* d, const uint32_t* a, const uint32_t* b) {
    asm volatile(
        "mma.sync.aligned.m16n8k8.row.col.f32.tf32.tf32.f32 "
        "{%0,%1,%2,%3}, {%4,%5,%6,%7}, {%8,%9}, {%0,%1,%2,%3};"
        : "+f"(d[0]), "+f"(d[1]), "+f"(d[2]), "+f"(d[3])
        : "r"(a[0]), "r"(a[1]), "r"(a[2]), "r"(a[3]), "r"(b[0]), "r"(b[1]));
}
__device__ __forceinline__ void cpa16(uint32_t dst, const void* src) {
    asm volatile("cp.async.cg.shared.global [%0], [%1], 16;" :: "r"(dst), "l"(src));
}
#define CPA_COMMIT() asm volatile("cp.async.commit_group;" ::: "memory")
#define CPA_WAIT1()  asm volatile("cp.async.wait_group 1;" ::: "memory")
__device__ __forceinline__ float gelu_exact(float g) {
    return 0.5f * g * (1.0f + erff(g * 0.70710678118654752f));
}
__device__ __forceinline__ int swzB(int k, int n) { return k * 128 + (n ^ ((k & 3) << 3)); }

// ---------------- pre-round x (router keeps raw x) ----------------
__global__ void round_x_kernel(const float* __restrict__ x, float* __restrict__ xr) {
    int i = blockIdx.x * 256 + threadIdx.x;    // over Nt*Dm/4
    float4 v = ((const float4*)x)[i];
    float4 o;
    o.x = rnd_tf32(v.x); o.y = rnd_tf32(v.y);
    o.z = rnd_tf32(v.z); o.w = rnd_tf32(v.w);
    ((float4*)xr)[i] = o;
}

// ---------------- routing ----------------
__global__ void router_kernel(const float* __restrict__ x,
                              const float* __restrict__ Wr,
                              const float* __restrict__ br) {
    int n = blockIdx.x;
    __shared__ float sx[Dm];
    __shared__ float slog[Ne];
    for (int k = threadIdx.x; k < Dm; k += blockDim.x) sx[k] = x[(long)n * Dm + k];
    __syncthreads();
    int e = threadIdx.x;
    if (e < Ne) {
        float s = 0.f;
        #pragma unroll 8
        for (int k = 0; k < Dm; k++) s += sx[k] * Wr[k * Ne + e];
        slog[e] = (s + br[e]) / TAUf;
    }
    __syncthreads();
    if (threadIdx.x == 0) {
        int i0 = 0; float v0 = slog[0];
        for (int j = 1; j < Ne; j++) if (slog[j] > v0) { v0 = slog[j]; i0 = j; }
        int i1 = -1; float v1 = -1e30f;
        for (int j = 0; j < Ne; j++) if (j != i0 && slog[j] > v1) { v1 = slog[j]; i1 = j; }
        float e1 = expf(v1 - v0);
        float z = 1.0f + e1;
        g_top[n * 2 + 0] = i0; g_top[n * 2 + 1] = i1;
        g_w[n * 2 + 0] = 1.0f / z; g_w[n * 2 + 1] = e1 / z;
    }
}

__global__ void __launch_bounds__(1024) dispatch_kernel() {
    __shared__ int scnt[Ne], soffs[Ne];
    int tid = threadIdx.x;
    if (tid < Ne) scnt[tid] = 0;
    __syncthreads();
    int rnk[4], eid[4];
    #pragma unroll
    for (int it = 0; it < 4; it++) {
        int i = tid + it * 1024;
        eid[it] = g_top[i];
        rnk[it] = atomicAdd(&scnt[eid[it]], 1);
    }
    __syncthreads();
    if (tid == 0) {
        int o = 0;
        for (int e2 = 0; e2 < Ne; e2++) { soffs[e2] = o; o += scnt[e2]; }
    }
    __syncthreads();
    #pragma unroll
    for (int it = 0; it < 4; it++) {
        int i = tid + it * 1024;
        int r = soffs[eid[it]] + rnk[it];
        g_tokrow[r] = i >> 1;
        g_slot[i] = r;
    }
    if (tid < Ne) { g_cnt[tid] = scnt[tid]; g_offs[tid] = soffs[tid]; }
    if (tid == 0) g_offs[Ne] = 2 * Nt;
}

// ---------------- TF32 mma.sync GEMM, cp.async 3-stage ----------------
// CTA tile 128x128x32. 256 threads = 8 warps (2M x 4N), warp tile 64x32.
// A data is pre-rounded to tf32 (xr / fused-epilogue outputs) -> no cvt on A frags.
#define BM 128
#define BK 32
#define STAGE_W 8192
#define NSTAGE 3
#define GEMM_SMEM_BYTES (NSTAGE * STAGE_W * 4)   // 98304

template <bool FUSED>
__global__ void __launch_bounds__(256, 2)
tf32gemm(const float* __restrict__ A,
         const float* __restrict__ Bb,
         const float* __restrict__ biasb,
         float* __restrict__ C,
         int Mfixed, int N, int W, int K,
         const int* __restrict__ cnt,
         const int* __restrict__ offs,
         const int* __restrict__ rowidx,
         long strideB, int strideBias) {
    extern __shared__ float sm[];
    uint32_t sb = smem_u32(sm);

    int tid = threadIdx.x;
    int w = tid >> 5, l = tid & 31;
    int g = l >> 2, c = l & 3;
    int wm = w >> 2, wn = w & 3;            // warp grid 2(M) x 4(N), warp tile 64x32

    int e = blockIdx.z;
    int M, rowbase;
    if (cnt) { M = cnt[e]; rowbase = offs[e]; }
    else     { M = Mfixed; rowbase = 0; }
    const float* B = Bb + (long)e * strideB;
    const float* bias = biasb + (long)e * strideBias;
    int bn = blockIdx.x * (FUSED ? 64 : 128);

    int am2 = tid >> 1;
    int ak = (tid & 1) << 4;
    int aswz = (am2 & 7) << 2;
    int bk = tid >> 3;
    int bc = tid & 7;
    int gcolB[4];
    #pragma unroll
    for (int i = 0; i < 4; i++) {
        int n4 = (bc + i * 8) << 2;
        if (FUSED) {
            int grp = n4 >> 4, sub = n4 & 15;
            gcolB[i] = bn + grp * 8 + sub + (sub >= 8 ? (W - 8) : 0);
        } else {
            gcolB[i] = bn + n4;
        }
    }
    int T = K / BK;

    for (int bm = blockIdx.y * BM; bm < M; bm += gridDim.y * BM) {
        int r = bm + am2;
        if (r >= M) r = bm;
        long ga = rowidx ? (long)rowidx[rowbase + r] : (long)(rowbase + r);
        const float* Arow = A + ga * (long)K;

        auto issue_stage = [&](int itg) {
            int kg = itg * BK;
            uint32_t base = sb + (uint32_t)((itg % NSTAGE) * STAGE_W * 4);
            uint32_t dA = base + (uint32_t)((am2 * 32) * 4);
            #pragma unroll
            for (int j = 0; j < 4; j++) {
                int kw = ak + (j << 2);
                cpa16(dA + (uint32_t)((kw ^ aswz) * 4), Arow + kg + kw);
            }
            #pragma unroll
            for (int i = 0; i < 4; i++) {
                int n4 = (bc + i * 8) << 2;
                cpa16(base + (uint32_t)((4096 + swzB(bk, n4)) * 4),
                      B + (long)(kg + bk) * N + gcolB[i]);
            }
        };

        float acc[4][4][4];
        #pragma unroll
        for (int mt = 0; mt < 4; mt++)
            #pragma unroll
            for (int nt = 0; nt < 4; nt++)
                #pragma unroll
                for (int i = 0; i < 4; i++) acc[mt][nt][i] = 0.f;

        issue_stage(0);
        CPA_COMMIT();
        if (T > 1) issue_stage(1);
        CPA_COMMIT();

        for (int it = 0; it < T; it++) {
            CPA_WAIT1();
            __syncthreads();
            if (it + 2 < T) issue_stage(it + 2);
            CPA_COMMIT();

            const float* As = sm + (it % NSTAGE) * STAGE_W;
            const float* Bs = As + 4096;
            #pragma unroll
            for (int ks = 0; ks < 4; ks++) {
                int kk = ks * 8;
                uint32_t af[4][4], bf[4][2];
                int kc = (kk + c) ^ (g << 2);
                int kc4 = (kk + c + 4) ^ (g << 2);
                #pragma unroll
                for (int mt = 0; mt < 4; mt++) {
                    int rm = wm * 64 + mt * 16 + g;
                    af[mt][0] = __float_as_uint(As[rm * 32 + kc]);          // pre-rounded
                    af[mt][1] = __float_as_uint(As[(rm + 8) * 32 + kc]);
                    af[mt][2] = __float_as_uint(As[rm * 32 + kc4]);
                    af[mt][3] = __float_as_uint(As[(rm + 8) * 32 + kc4]);
                }
                #pragma unroll
                for (int nt = 0; nt < 4; nt++) {
                    int cn = (wn * 32 + nt * 8 + g) ^ (c << 3);
                    bf[nt][0] = f2tf32(Bs[(kk + c) * 128 + cn]);
                    bf[nt][1] = f2tf32(Bs[(kk + c + 4) * 128 + cn]);
                }
                #pragma unroll
                for (int mt = 0; mt < 4; mt++)
                    #pragma unroll
                    for (int nt = 0; nt < 4; nt++)
                        mma_tf32(acc[mt][nt], af[mt], bf[nt]);
            }
        }

        // ---- epilogue ----
        if (FUSED) {
            // write tf32-rounded GEGLU output: identical to what GEMM2 would
            // have produced by rounding at fragment load (cvt is idempotent).
            #pragma unroll
            for (int mt = 0; mt < 4; mt++) {
                int rm0 = bm + wm * 64 + mt * 16 + g;
                #pragma unroll
                for (int np = 0; np < 2; np++) {
                    int j0 = bn + (wn * 2 + np) * 8 + 2 * c;
                    float2 ba = *(const float2*)(bias + j0);
                    float2 bg = *(const float2*)(bias + W + j0);
                    float* a = acc[mt][2 * np];
                    float* gt = acc[mt][2 * np + 1];
                    if (rm0 < M) {
                        float2 o;
                        o.x = rnd_tf32((a[0] + ba.x) * gelu_exact(gt[0] + bg.x));
                        o.y = rnd_tf32((a[1] + ba.y) * gelu_exact(gt[1] + bg.y));
                        *(float2*)(C + (long)(rowbase + rm0) * W + j0) = o;
                    }
                    if (rm0 + 8 < M) {
                        float2 o;
                        o.x = rnd_tf32((a[2] + ba.x) * gelu_exact(gt[2] + bg.x));
                        o.y = rnd_tf32((a[3] + ba.y) * gelu_exact(gt[3] + bg.y));
                        *(float2*)(C + (long)(rowbase + rm0 + 8) * W + j0) = o;
                    }
                }
            }
        } else {
            #pragma unroll
            for (int mt = 0; mt < 4; mt++) {
                int rm0 = bm + wm * 64 + mt * 16 + g;
                #pragma unroll
                for (int nt = 0; nt < 4; nt++) {
                    int col = bn + wn * 32 + nt * 8 + 2 * c;
                    float2 bv = *(const float2*)(bias + col);
                    if (rm0 < M) {
                        float2 o;
                        o.x = acc[mt][nt][0] + bv.x;
                        o.y = acc[mt][nt][1] + bv.y;
                        *(float2*)(C + (long)(rowbase + rm0) * W + col) = o;
                    }
                    if (rm0 + 8 < M) {
                        float2 o;
                        o.x = acc[mt][nt][2] + bv.x;
                        o.y = acc[mt][nt][3] + bv.y;
                        *(float2*)(C + (long)(rowbase + rm0 + 8) * W + col) = o;
                    }
                }
            }
        }
        __syncthreads();
    }
}

// ---------------- combine ----------------
__global__ void combine_kernel(const float* __restrict__ ys,
                               const float* __restrict__ yE,
                               float* __restrict__ out) {
    int idx = blockIdx.x * blockDim.x + threadIdx.x;
    int n = idx >> 8;
    int d4 = (idx & 255) << 2;
    int s0 = g_slot[n * 2 + 0], s1 = g_slot[n * 2 + 1];
    float w0 = g_w[n * 2 + 0], w1 = g_w[n * 2 + 1];
    float4 a = *(const float4*)(ys + (long)n * Dm + d4);
    float4 b = *(const float4*)(yE + (long)s0 * Dm + d4);
    float4 cc = *(const float4*)(yE + (long)s1 * Dm + d4);
    float4 o;
    o.x = a.x + w0 * b.x + w1 * cc.x;
    o.y = a.y + w0 * b.y + w1 * cc.y;
    o.z = a.z + w0 * b.z + w1 * cc.z;
    o.w = a.w + w0 * b.w + w1 * cc.w;
    *(float4*)(out + (long)n * Dm + d4) = o;
}

// ---------------- launch ----------------
extern "C" void kernel_launch(void* const* d_in, const int* in_sizes, int n_in,
                              void* d_out, int out_size) {
    const float* x   = (const float*)d_in[0];
    const float* Ws1 = (const float*)d_in[1];
    const float* bs1 = (const float*)d_in[2];
    const float* Ws2 = (const float*)d_in[3];
    const float* bs2 = (const float*)d_in[4];
    const float* We1 = (const float*)d_in[5];
    const float* be1 = (const float*)d_in[6];
    const float* We2 = (const float*)d_in[7];
    const float* be2 = (const float*)d_in[8];
    const float* Wr  = (const float*)d_in[9];
    const float* br  = (const float*)d_in[10];
    float* out = (float*)d_out;

    float *pxr, *pAact, *pys, *pAr, *pyE;
    int *pcnt, *poffs, *ptok;
    cudaGetSymbolAddress((void**)&pxr,   g_xr);
    cudaGetSymbolAddress((void**)&pAact, g_Aact);
    cudaGetSymbolAddress((void**)&pys,   g_ys);
    cudaGetSymbolAddress((void**)&pAr,   g_Ar);
    cudaGetSymbolAddress((void**)&pyE,   g_yE);
    cudaGetSymbolAddress((void**)&pcnt,  g_cnt);
    cudaGetSymbolAddress((void**)&poffs, g_offs);
    cudaGetSymbolAddress((void**)&ptok,  g_tokrow);

    cudaFuncSetAttribute(tf32gemm<true>,  cudaFuncAttributeMaxDynamicSharedMemorySize, GEMM_SMEM_BYTES);
    cudaFuncSetAttribute(tf32gemm<false>, cudaFuncAttributeMaxDynamicSharedMemorySize, GEMM_SMEM_BYTES);

    // 0) pre-round x for GEMM A-side (router uses raw x)
    round_x_kernel<<<(Nt * Dm / 4) / 256, 256>>>(x, pxr);

    // 1) routing
    router_kernel<<<Nt, 128>>>(x, Wr, br);
    dispatch_kernel<<<1, 1024>>>();

    // 2) GEMM1 (fused GEGLU, rounded outputs): shared then routed
    tf32gemm<true><<<dim3(HSdim / 64, Nt / BM, 1), 256, GEMM_SMEM_BYTES>>>(
        pxr, Ws1, bs1, pAact, Nt, 2 * HSdim, HSdim, Dm,
        nullptr, nullptr, nullptr, 0, 0);
    tf32gemm<true><<<dim3(HRdim / 64, 4, Ne), 256, GEMM_SMEM_BYTES>>>(
        pxr, We1, be1, pAr, 0, 2 * HRdim, HRdim, Dm,
        pcnt, poffs, ptok, (long)Dm * 2 * HRdim, 2 * HRdim);

    // 3) GEMM2: shared then routed
    tf32gemm<false><<<dim3(Dm / 128, Nt / BM, 1), 256, GEMM_SMEM_BYTES>>>(
        pAact, Ws2, bs2, pys, Nt, Dm, Dm, HSdim,
        nullptr, nullptr, nullptr, 0, 0);
    tf32gemm<false><<<dim3(Dm / 128, 5, Ne), 256, GEMM_SMEM_BYTES>>>(
        pAr, We2, be2, pyE, 0, Dm, Dm, HRdim,
        pcnt, poffs, nullptr, (long)HRdim * Dm, Dm);

    // 4) combine
    combine_kernel<<<(Nt * Dm / 4) / 256, 256>>>(pys, pyE, out);
}